// round 1
// baseline (speedup 1.0000x reference)
#include <cuda_runtime.h>

#define N_SAMPLES 8192
#define N_CHANNELS 1024
#define N_COMP 4
#define SAMPLES_PER_BLOCK 16
#define THREADS 256

// padded component row: 8 zero floats front + 1024 + 8 zero floats back
#define ROW_PAD 8
#define ROW_LEN (N_CHANNELS + 2 * ROW_PAD)   // 1040 floats, 4160 B (16B-aligned stride)

__global__ void __launch_bounds__(THREADS)
smf_kernel(const float* __restrict__ comp,      // [4, 1024]
           const float* __restrict__ contrib,   // [8192, 4]
           const float* __restrict__ shift,     // [8192, 4]
           float* __restrict__ out)             // [8192, 1024]
{
    __shared__ __align__(16) float scomp[N_COMP * ROW_LEN];
    __shared__ float s_shift[SAMPLES_PER_BLOCK * N_COMP];
    __shared__ float s_contrib[SAMPLES_PER_BLOCK * N_COMP];

    const int tid = threadIdx.x;
    const int sbase = blockIdx.x * SAMPLES_PER_BLOCK;

    // Load components into padded smem rows (pads zeroed -> branch-free boundary).
    #pragma unroll
    for (int idx = tid; idx < N_COMP * ROW_LEN; idx += THREADS) {
        int k = idx / ROW_LEN;
        int p = idx - k * ROW_LEN;
        int j = p - ROW_PAD;
        float v = 0.0f;
        if (j >= 0 && j < N_CHANNELS) v = comp[k * N_CHANNELS + j];
        scomp[idx] = v;
    }
    // Per-block sample params (16 samples x 4 comps).
    if (tid < SAMPLES_PER_BLOCK * N_COMP) {
        s_shift[tid]   = shift[sbase * N_COMP + tid];
        s_contrib[tid] = contrib[sbase * N_COMP + tid];
    }
    __syncthreads();

    const int i0 = tid * 4;   // 4 consecutive channels per thread

    #pragma unroll 2
    for (int s = 0; s < SAMPLES_PER_BLOCK; s++) {
        const int sample = sbase + s;
        float4 acc = make_float4(0.f, 0.f, 0.f, 0.f);

        #pragma unroll
        for (int k = 0; k < N_COMP; k++) {
            // warp-uniform per-(sample,k) parameters
            const float sh = s_shift[s * N_COMP + k];
            const float cn = s_contrib[s * N_COMP + k];
            const float ff = floorf(sh);
            const int   fi = (int)ff;
            const float fr = sh - ff;
            const float b  = cn * fr;         // weight of tap j+1
            const float a  = cn - b;          // cn*(1-fr), weight of tap j

            // 5-tap window comp[k][i0+fi .. i0+fi+4], padded index p in [4,1032]
            const int p = i0 + fi + ROW_PAD;
            const int q = p >> 2;             // aligned float4 index (lane-consecutive)
            const int r = p & 3;              // uniform across warp (i0 % 4 == 0)

            const float4* row = reinterpret_cast<const float4*>(&scomp[k * ROW_LEN]);
            const float4 v0 = row[q];
            const float4 v1 = row[q + 1];

            float w0, w1, w2, w3, w4;
            switch (r) {                       // uniform branch
                case 0:  w0 = v0.x; w1 = v0.y; w2 = v0.z; w3 = v0.w; w4 = v1.x; break;
                case 1:  w0 = v0.y; w1 = v0.z; w2 = v0.w; w3 = v1.x; w4 = v1.y; break;
                case 2:  w0 = v0.z; w1 = v0.w; w2 = v1.x; w3 = v1.y; w4 = v1.z; break;
                default: w0 = v0.w; w1 = v1.x; w2 = v1.y; w3 = v1.z; w4 = v1.w; break;
            }

            acc.x += a * w0 + b * w1;
            acc.y += a * w1 + b * w2;
            acc.z += a * w2 + b * w3;
            acc.w += a * w3 + b * w4;
        }

        reinterpret_cast<float4*>(out)[sample * (N_CHANNELS / 4) + tid] = acc;
    }
}

extern "C" void kernel_launch(void* const* d_in, const int* in_sizes, int n_in,
                              void* d_out, int out_size)
{
    // metadata order: inputs [8192,1024] (ignored), components [4,1024],
    // contributions [8192,4], shift [8192,4]
    const float* comp    = (const float*)d_in[1];
    const float* contrib = (const float*)d_in[2];
    const float* shift   = (const float*)d_in[3];
    float* out           = (float*)d_out;

    const int blocks = N_SAMPLES / SAMPLES_PER_BLOCK;   // 512
    smf_kernel<<<blocks, THREADS>>>(comp, contrib, shift, out);
}